// round 16
// baseline (speedup 1.0000x reference)
#include <cuda_runtime.h>
#include <cuda_bf16.h>
#include <math.h>
#include <stdint.h>

// Problem constants
#define B_   2
#define N_   2048
#define BQ_  32
#define BK_  128
#define NB_  64
#define CS_  384
#define CZ_  128
#define CH_  16
#define H_   12
#define PQK_ 4
#define PV_  8
#define ROWS_ (B_ * N_)          // 4096
#define PROJC_ 1152
#define FEATC_ 960

// -------- scratch (static device globals; no allocation) --------
__device__ float g_sN   [ROWS_ * CS_];
__device__ float g_proj [ROWS_ * PROJC_];
__device__ float g_qpts [ROWS_ * 144];
__device__ float g_kvpts[ROWS_ * 432];
__device__ float g_qn   [ROWS_ * 12];
__device__ float g_kn   [ROWS_ * 12];
__device__ float g_feats[ROWS_ * FEATC_];
__device__ float g_Wcat [CS_ * PROJC_];
__device__ float g_Wzc  [CZ_ * 44];

// -------- helpers --------
__device__ __forceinline__ float warpSum(float v) {
#pragma unroll
    for (int o = 16; o; o >>= 1) v += __shfl_xor_sync(0xffffffffu, v, o);
    return v;
}
__device__ __forceinline__ float warpMax(float v) {
#pragma unroll
    for (int o = 16; o; o >>= 1) v = fmaxf(v, __shfl_xor_sync(0xffffffffu, v, o));
    return v;
}
__device__ __forceinline__ uint32_t f2tf32(float f) {
    uint32_t r;
    asm("cvt.rna.tf32.f32 %0, %1;" : "=r"(r) : "f"(f));
    return r;
}
__device__ __forceinline__ void mma_tf32(float* c, const uint32_t* a, const uint32_t* b) {
    asm volatile("mma.sync.aligned.m16n8k8.row.col.f32.tf32.tf32.f32 "
                 "{%0,%1,%2,%3}, {%4,%5,%6,%7}, {%8,%9}, {%0,%1,%2,%3};"
                 : "+f"(c[0]), "+f"(c[1]), "+f"(c[2]), "+f"(c[3])
                 : "r"(a[0]), "r"(a[1]), "r"(a[2]), "r"(a[3]), "r"(b[0]), "r"(b[1]));
}
// fp32-accurate MMA via 3-term tf32 split: c += a*b
__device__ __forceinline__ void mma_split(float* c, const float a[4], const float b[2]) {
    uint32_t ahi[4], alo[4], bhi[2], blo[2];
#pragma unroll
    for (int i = 0; i < 4; i++) {
        ahi[i] = f2tf32(a[i]);
        alo[i] = f2tf32(a[i] - __uint_as_float(ahi[i]));
    }
#pragma unroll
    for (int i = 0; i < 2; i++) {
        bhi[i] = f2tf32(b[i]);
        blo[i] = f2tf32(b[i] - __uint_as_float(bhi[i]));
    }
    mma_tf32(c, ahi, bhi);
    mma_tf32(c, ahi, blo);
    mma_tf32(c, alo, bhi);
}

// -------- weight prep --------
__global__ void prep_weights(const float* __restrict__ Wq, const float* __restrict__ Wk,
                             const float* __restrict__ Wv, const float* __restrict__ Wqp,
                             const float* __restrict__ Wkvp, const float* __restrict__ Wb,
                             const float* __restrict__ Wdz) {
    const int total1 = CS_ * PROJC_;
    const int total = total1 + CZ_ * 44;
    for (int i = blockIdx.x * blockDim.x + threadIdx.x; i < total; i += gridDim.x * blockDim.x) {
        if (i < total1) {
            int r = i / PROJC_, c = i % PROJC_;
            float w;
            if (c < 192)      w = Wq  [r * 192 + c] * 0.14433756729740643f;
            else if (c < 384) w = Wk  [r * 192 + (c - 192)];
            else if (c < 576) w = Wv  [r * 192 + (c - 384)];
            else if (c < 720) w = Wqp [r * 144 + (c - 576)];
            else              w = Wkvp[r * 432 + (c - 720)];
            g_Wcat[i] = w;
        } else {
            int j = i - total1;
            int r = j / 44, c = j % 44;
            g_Wzc[j] = (c < 12) ? Wb[r * 12 + c] * 0.5773502691896258f
                                : Wdz[r * 32 + (c - 12)];
        }
    }
}

// -------- LayerNorm of s --------
__global__ __launch_bounds__(128) void ln_s_kernel(const float* __restrict__ s,
                                                   const float* __restrict__ g,
                                                   const float* __restrict__ bb) {
    const int row = blockIdx.x;
    const int t = threadIdx.x;
    const float* x = s + (size_t)row * CS_;
    float a0 = x[t], a1 = x[t + 128], a2 = x[t + 256];
    float sum = a0 + a1 + a2;
    float sq = a0 * a0 + a1 * a1 + a2 * a2;
    __shared__ float rs[4], rq[4];
    float ws = warpSum(sum), wq = warpSum(sq);
    if ((t & 31) == 0) { rs[t >> 5] = ws; rq[t >> 5] = wq; }
    __syncthreads();
    float S = rs[0] + rs[1] + rs[2] + rs[3];
    float Q = rq[0] + rq[1] + rq[2] + rq[3];
    float m = S * (1.0f / 384.0f);
    float var = Q * (1.0f / 384.0f) - m * m;
    float inv = rsqrtf(var + 1e-5f);
    float* o = g_sN + (size_t)row * CS_;
    o[t]       = (a0 - m) * inv * g[t]       + bb[t];
    o[t + 128] = (a1 - m) * inv * g[t + 128] + bb[t + 128];
    o[t + 256] = (a2 - m) * inv * g[t + 256] + bb[t + 256];
}

// -------- tf32 tensor-core GEMM, 2-stage smem pipeline --------
__global__ __launch_bounds__(256) void tgemm128(const float* __restrict__ A,
                                                const float* __restrict__ B,
                                                float* __restrict__ C,
                                                int M, int N, int K) {
    __shared__ __align__(16) uint32_t As[2][16][136];
    __shared__ __align__(16) uint32_t Bs[2][16][136];
    const int tid = threadIdx.x;
    const int bm = blockIdx.y << 7, bn = blockIdx.x << 7;
    const int ar = tid >> 2, ac = (tid & 3) << 2;
    const int br = tid >> 5, bc = (tid & 31) << 2;
    const int warp = tid >> 5, lane = tid & 31;
    const int wm = (warp >> 2) * 64, wn = (warp & 3) * 32;
    const int gid = lane >> 2, tig = lane & 3;

    const float* Ap = A + (size_t)(bm + ar) * K + ac;
    const float* Bp = B + (size_t)br * N + bn + bc;
    const size_t A64 = (size_t)64 * K;
    const size_t B8  = (size_t)8 * N;

    float4 pa0 = *reinterpret_cast<const float4*>(Ap);
    float4 pa1 = *reinterpret_cast<const float4*>(Ap + A64);
    float4 pb0 = *reinterpret_cast<const float4*>(Bp);
    float4 pb1 = *reinterpret_cast<const float4*>(Bp + B8);

    As[0][ac + 0][ar] = f2tf32(pa0.x); As[0][ac + 1][ar] = f2tf32(pa0.y);
    As[0][ac + 2][ar] = f2tf32(pa0.z); As[0][ac + 3][ar] = f2tf32(pa0.w);
    As[0][ac + 0][ar + 64] = f2tf32(pa1.x); As[0][ac + 1][ar + 64] = f2tf32(pa1.y);
    As[0][ac + 2][ar + 64] = f2tf32(pa1.z); As[0][ac + 3][ar + 64] = f2tf32(pa1.w);
    Bs[0][br][bc + 0] = f2tf32(pb0.x); Bs[0][br][bc + 1] = f2tf32(pb0.y);
    Bs[0][br][bc + 2] = f2tf32(pb0.z); Bs[0][br][bc + 3] = f2tf32(pb0.w);
    Bs[0][br + 8][bc + 0] = f2tf32(pb1.x); Bs[0][br + 8][bc + 1] = f2tf32(pb1.y);
    Bs[0][br + 8][bc + 2] = f2tf32(pb1.z); Bs[0][br + 8][bc + 3] = f2tf32(pb1.w);
    __syncthreads();

    float acc[16][4] = {};
    const int ktiles = K >> 4;
    for (int kt = 0; kt < ktiles; kt++) {
        const int cur = kt & 1;
        const bool more = (kt + 1 < ktiles);
        if (more) {
            Ap += 16; Bp += (size_t)16 * N;
            pa0 = *reinterpret_cast<const float4*>(Ap);
            pa1 = *reinterpret_cast<const float4*>(Ap + A64);
            pb0 = *reinterpret_cast<const float4*>(Bp);
            pb1 = *reinterpret_cast<const float4*>(Bp + B8);
        }
#pragma unroll
        for (int kk = 0; kk < 16; kk += 8) {
            uint32_t af[4][4], bf[4][2];
#pragma unroll
            for (int mt = 0; mt < 4; mt++) {
                int m = wm + mt * 16 + gid;
                af[mt][0] = As[cur][kk + tig][m];
                af[mt][1] = As[cur][kk + tig][m + 8];
                af[mt][2] = As[cur][kk + tig + 4][m];
                af[mt][3] = As[cur][kk + tig + 4][m + 8];
            }
#pragma unroll
            for (int nt = 0; nt < 4; nt++) {
                int n = wn + nt * 8 + gid;
                bf[nt][0] = Bs[cur][kk + tig][n];
                bf[nt][1] = Bs[cur][kk + tig + 4][n];
            }
#pragma unroll
            for (int mt = 0; mt < 4; mt++)
#pragma unroll
                for (int nt = 0; nt < 4; nt++)
                    mma_tf32(acc[mt * 4 + nt], af[mt], bf[nt]);
        }
        if (more) {
            const int nxt = cur ^ 1;
            As[nxt][ac + 0][ar] = f2tf32(pa0.x); As[nxt][ac + 1][ar] = f2tf32(pa0.y);
            As[nxt][ac + 2][ar] = f2tf32(pa0.z); As[nxt][ac + 3][ar] = f2tf32(pa0.w);
            As[nxt][ac + 0][ar + 64] = f2tf32(pa1.x); As[nxt][ac + 1][ar + 64] = f2tf32(pa1.y);
            As[nxt][ac + 2][ar + 64] = f2tf32(pa1.z); As[nxt][ac + 3][ar + 64] = f2tf32(pa1.w);
            Bs[nxt][br][bc + 0] = f2tf32(pb0.x); Bs[nxt][br][bc + 1] = f2tf32(pb0.y);
            Bs[nxt][br][bc + 2] = f2tf32(pb0.z); Bs[nxt][br][bc + 3] = f2tf32(pb0.w);
            Bs[nxt][br + 8][bc + 0] = f2tf32(pb1.x); Bs[nxt][br + 8][bc + 1] = f2tf32(pb1.y);
            Bs[nxt][br + 8][bc + 2] = f2tf32(pb1.z); Bs[nxt][br + 8][bc + 3] = f2tf32(pb1.w);
            __syncthreads();
        }
    }
#pragma unroll
    for (int mt = 0; mt < 4; mt++) {
#pragma unroll
        for (int nt = 0; nt < 4; nt++) {
            const float* a = acc[mt * 4 + nt];
            int r0 = bm + wm + mt * 16 + gid;
            int c0 = bn + wn + nt * 8 + tig * 2;
            float2 lo = make_float2(a[0], a[1]);
            float2 hi = make_float2(a[2], a[3]);
            *reinterpret_cast<float2*>(&C[(size_t)r0 * N + c0]) = lo;
            *reinterpret_cast<float2*>(&C[(size_t)(r0 + 8) * N + c0]) = hi;
        }
    }
}

// -------- per-row point rotation + norms --------
__global__ __launch_bounds__(192) void postproj(const float* __restrict__ rots,
                                                const float* __restrict__ trans) {
    const int row = blockIdx.x;
    const int t = threadIdx.x;
    __shared__ float R[9], T[3], nrm[24];
    if (t < 9)  R[t] = rots[row * 9 + t];
    if (t < 3)  T[t] = trans[row * 3 + t];
    if (t < 24) nrm[t] = 0.0f;
    __syncthreads();
    const float* pr = g_proj + (size_t)row * PROJC_;
    float x, y, zz;
    if (t < 48) {
        x = pr[576 + t * 3]; y = pr[576 + t * 3 + 1]; zz = pr[576 + t * 3 + 2];
    } else {
        int j = t - 48;
        x = pr[720 + j * 3]; y = pr[720 + j * 3 + 1]; zz = pr[720 + j * 3 + 2];
    }
    float rx = R[0] * x + R[1] * y + R[2] * zz + T[0];
    float ry = R[3] * x + R[4] * y + R[5] * zz + T[1];
    float rz = R[6] * x + R[7] * y + R[8] * zz + T[2];
    float sq = rx * rx + ry * ry + rz * rz;
    if (t < 48) {
        g_qpts[row * 144 + t * 3 + 0] = rx;
        g_qpts[row * 144 + t * 3 + 1] = ry;
        g_qpts[row * 144 + t * 3 + 2] = rz;
        atomicAdd(&nrm[t >> 2], sq);
    } else {
        int j = t - 48;
        g_kvpts[(size_t)row * 432 + j * 3 + 0] = rx;
        g_kvpts[(size_t)row * 432 + j * 3 + 1] = ry;
        g_kvpts[(size_t)row * 432 + j * 3 + 2] = rz;
        if ((j % 12) < 4) atomicAdd(&nrm[12 + j / 12], sq);
    }
    __syncthreads();
    if (t < 12)       g_qn[row * 12 + t] = nrm[t];
    else if (t < 24)  g_kn[row * 12 + (t - 12)] = nrm[t];
}

// -------- fused attention kernel: one block per (b, nb, group of 4 q) --------
struct AttnSmem {
    float zn[128][132];        // LN'd z for the CURRENT q (reused across the 4 q)
    float logit[4][12][132];   // logit base -> +bbias -> probs (row pad 132 for MMA)
    float y[4][12][128];       // a @ zn per q
    float WbT[16][132];        // transposed pre-scaled bbias weights (rows 12..15 zero)
    float q[4][192];
    float qpts[4][144];
    float qn[4][12];
    float hw[12];
    float R[4][9], t[4][3];
    float km[128];
    float qm[4];
    float opt[4][288];
    int   o1[128], o2[128], o3[128];
};

__global__ __launch_bounds__(512) void attn_kernel(const float* __restrict__ z,
                                                   const float* __restrict__ trans,
                                                   const float* __restrict__ rots,
                                                   const float* __restrict__ s_mask,
                                                   const int* __restrict__ key_idx,
                                                   const float* __restrict__ ln_z_g,
                                                   const float* __restrict__ ln_z_b,
                                                   const float* __restrict__ head_w) {
    extern __shared__ __align__(16) char smem_raw[];
    AttnSmem& S = *reinterpret_cast<AttnSmem*>(smem_raw);

    const int blk = blockIdx.x;
    const int b  = blk >> 9;
    const int nb = (blk >> 3) & 63;
    const int q0 = (blk & 7) * 4;
    const int tid = threadIdx.x;
    const int lane = tid & 31, warp = tid >> 5;
    const int gid = lane >> 2, tig = lane & 3;
    const int row0 = b * N_ + nb * 32 + q0;

    // ---- prefetch q0's z into registers immediately ----
    const float4* zb_base = reinterpret_cast<const float4*>(
        z + ((size_t)((b * 64 + nb) * 32 + q0) * 128) * 128);
    float4 zr[8];
#pragma unroll
    for (int j = 0; j < 8; j++)
        zr[j] = zb_base[(size_t)(warp * 8 + j) * 32 + lane];

    // ---- init ----
    for (int k = tid; k < 128; k += 512) {
        int nk = key_idx[nb * 128 + k];
        int kr = b * N_ + nk;
        S.o1[k] = kr * PROJC_;
        S.o2[k] = kr * 432;
        S.o3[k] = kr * 12;
        S.km[k] = s_mask[kr];
    }
    for (int i = tid; i < 16 * 132; i += 512) {
        int col = i / 132, c = i % 132;
        S.WbT[col][c] = (col < 12 && c < 128) ? g_Wzc[c * 44 + col] : 0.0f;
    }
    for (int i = tid; i < 4 * 192; i += 512)
        S.q[i / 192][i % 192] = g_proj[(size_t)(row0 + i / 192) * PROJC_ + i % 192];
    for (int i = tid; i < 4 * 144; i += 512)
        S.qpts[i / 144][i % 144] = g_qpts[(row0 + i / 144) * 144 + i % 144];
    if (tid < 48) S.qn[tid / 12][tid % 12] = g_qn[(row0 + tid / 12) * 12 + tid % 12];
    if (tid < 36) S.R[tid / 9][tid % 9] = rots[(row0 + tid / 9) * 9 + tid % 9];
    if (tid >= 64 && tid < 76) S.t[(tid - 64) / 3][(tid - 64) % 3] = trans[(row0 + (tid - 64) / 3) * 3 + (tid - 64) % 3];
    if (tid >= 96 && tid < 100) S.qm[tid - 96] = s_mask[row0 + (tid - 96)];
    if (tid >= 128 && tid < 140) {
        float hx = head_w[tid - 128];
        float sp = fmaxf(hx, 0.0f) + log1pf(expf(-fabsf(hx)));
        S.hw[tid - 128] = -0.5f * sp * 0.13608276348795434f;
    }
    __syncthreads();

    // ---- phase A: logit base for all 4 q (gathers amortized 4x) ----
#pragma unroll
    for (int l = tid; l < 1536; l += 512) {
        int h = l >> 7, k = l & 127;
        const float* kp = g_proj + S.o1[k] + 192 + h * 16;
        float4 k0 = __ldg((const float4*)(kp));
        float4 k1 = __ldg((const float4*)(kp + 4));
        float4 k2 = __ldg((const float4*)(kp + 8));
        float4 k3 = __ldg((const float4*)(kp + 12));
        const float* kpt = g_kvpts + S.o2[k] + h * 36;
        float4 p0 = __ldg((const float4*)(kpt));
        float4 p1 = __ldg((const float4*)(kpt + 4));
        float4 p2 = __ldg((const float4*)(kpt + 8));
        float knv = __ldg(&g_kn[S.o3[k] + h]);
        const float hwv = S.hw[h];
        const float kmv = S.km[k];
#pragma unroll
        for (int i = 0; i < 4; i++) {
            float4 q0v = *reinterpret_cast<const float4*>(&S.q[i][h * 16]);
            float4 q1v = *reinterpret_cast<const float4*>(&S.q[i][h * 16 + 4]);
            float4 q2v = *reinterpret_cast<const float4*>(&S.q[i][h * 16 + 8]);
            float4 q3v = *reinterpret_cast<const float4*>(&S.q[i][h * 16 + 12]);
            float4 s0 = *reinterpret_cast<const float4*>(&S.qpts[i][h * 12]);
            float4 s1 = *reinterpret_cast<const float4*>(&S.qpts[i][h * 12 + 4]);
            float4 s2 = *reinterpret_cast<const float4*>(&S.qpts[i][h * 12 + 8]);
            float dot = k0.x * q0v.x + k0.y * q0v.y + k0.z * q0v.z + k0.w * q0v.w
                      + k1.x * q1v.x + k1.y * q1v.y + k1.z * q1v.z + k1.w * q1v.w
                      + k2.x * q2v.x + k2.y * q2v.y + k2.z * q2v.z + k2.w * q2v.w
                      + k3.x * q3v.x + k3.y * q3v.y + k3.z * q3v.z + k3.w * q3v.w;
            float pdot = p0.x * s0.x + p0.y * s0.y + p0.z * s0.z + p0.w * s0.w
                       + p1.x * s1.x + p1.y * s1.y + p1.z * s1.z + p1.w * s1.w
                       + p2.x * s2.x + p2.y * s2.y + p2.z * s2.z + p2.w * s2.w;
            float pt = -2.0f * pdot + S.qn[i][h] + knv;
            S.logit[i][h][k] = dot + hwv * pt + 100000.0f * (S.qm[i] * kmv - 1.0f);
        }
    }
    __syncthreads();

    // ---- phase B: per q: LN(regs) -> bbias(MMA) -> softmax -> y(MMA) ----
    const float4 gv = reinterpret_cast<const float4*>(ln_z_g)[lane];
    const float4 bv = reinterpret_cast<const float4*>(ln_z_b)[lane];
    for (int iq = 0; iq < 4; iq++) {
#pragma unroll
        for (int i = 0; i < 4; i++) {
            const int k0 = warp * 8 + i * 2;
            float4 u = zr[i * 2], w = zr[i * 2 + 1];
            float su = u.x + u.y + u.z + u.w;
            float sw = w.x + w.y + w.z + w.w;
            float qu = u.x * u.x + u.y * u.y + u.z * u.z + u.w * u.w;
            float qw = w.x * w.x + w.y * w.y + w.z * w.z + w.w * w.w;
            float mu = warpSum(su) * (1.0f / 128.0f);
            float mw = warpSum(sw) * (1.0f / 128.0f);
            float vu = warpSum(qu) * (1.0f / 128.0f) - mu * mu;
            float vw = warpSum(qw) * (1.0f / 128.0f) - mw * mw;
            float iu = rsqrtf(vu + 1e-5f);
            float iw = rsqrtf(vw + 1e-5f);
            float4 ou, ow;
            ou.x = (u.x - mu) * iu * gv.x + bv.x; ou.y = (u.y - mu) * iu * gv.y + bv.y;
            ou.z = (u.z - mu) * iu * gv.z + bv.z; ou.w = (u.w - mu) * iu * gv.w + bv.w;
            ow.x = (w.x - mw) * iw * gv.x + bv.x; ow.y = (w.y - mw) * iw * gv.y + bv.y;
            ow.z = (w.z - mw) * iw * gv.z + bv.z; ow.w = (w.w - mw) * iw * gv.w + bv.w;
            *reinterpret_cast<float4*>(&S.zn[k0][lane * 4])     = ou;
            *reinterpret_cast<float4*>(&S.zn[k0 + 1][lane * 4]) = ow;
        }
        if (iq < 3) {
            const float4* zb = zb_base + (size_t)(iq + 1) * 4096;
#pragma unroll
            for (int j = 0; j < 8; j++)
                zr[j] = zb[(size_t)(warp * 8 + j) * 32 + lane];
        }
        __syncthreads();

        // bbias via MMA: bb[128key, 12col] = zn[128,128] @ Wb[128,12]
        {
            const int mt = warp >> 1, nt = warp & 1;
            const int m0 = mt * 16, n0 = nt * 8;
            float c[4] = {};
#pragma unroll
            for (int ko = 0; ko < 128; ko += 8) {
                float a[4], bb[2];
                a[0] = S.zn[m0 + gid][ko + tig];
                a[1] = S.zn[m0 + gid + 8][ko + tig];
                a[2] = S.zn[m0 + gid][ko + tig + 4];
                a[3] = S.zn[m0 + gid + 8][ko + tig + 4];
                bb[0] = S.WbT[n0 + gid][ko + tig];
                bb[1] = S.WbT[n0 + gid][ko + tig + 4];
                mma_split(c, a, bb);
            }
            const int col0 = n0 + 2 * tig;
            if (col0 < 12) {
                S.logit[iq][col0][m0 + gid]     += c[0];
                S.logit[iq][col0][m0 + gid + 8] += c[2];
            }
            if (col0 + 1 < 12) {
                S.logit[iq][col0 + 1][m0 + gid]     += c[1];
                S.logit[iq][col0 + 1][m0 + gid + 8] += c[3];
            }
        }
        __syncthreads();

        // softmax
        if (warp < 12) {
            const int h = warp;
            float v0 = S.logit[iq][h][lane],      v1 = S.logit[iq][h][lane + 32];
            float v2 = S.logit[iq][h][lane + 64], v3 = S.logit[iq][h][lane + 96];
            float mx = warpMax(fmaxf(fmaxf(v0, v1), fmaxf(v2, v3)));
            v0 = expf(v0 - mx); v1 = expf(v1 - mx); v2 = expf(v2 - mx); v3 = expf(v3 - mx);
            float invs = 1.0f / warpSum(v0 + v1 + v2 + v3);
            S.logit[iq][h][lane]      = v0 * invs;
            S.logit[iq][h][lane + 32] = v1 * invs;
            S.logit[iq][h][lane + 64] = v2 * invs;
            S.logit[iq][h][lane + 96] = v3 * invs;
        }
        __syncthreads();

        // y via MMA: y[12h, 128cz] = a[12,128k] @ zn[128k,128cz]
        {
            const int n0 = warp * 8;
            float c[4] = {};
            const bool hiRow = (gid + 8 < 12);
#pragma unroll
            for (int ko = 0; ko < 128; ko += 8) {
                float a[4], bb[2];
                a[0] = S.logit[iq][gid][ko + tig];
                a[1] = hiRow ? S.logit[iq][gid + 8][ko + tig] : 0.0f;
                a[2] = S.logit[iq][gid][ko + tig + 4];
                a[3] = hiRow ? S.logit[iq][gid + 8][ko + tig + 4] : 0.0f;
                bb[0] = S.zn[ko + tig][n0 + gid];
                bb[1] = S.zn[ko + tig + 4][n0 + gid];
                mma_split(c, a, bb);
            }
            S.y[iq][gid][n0 + 2 * tig]     = c[0];
            S.y[iq][gid][n0 + 2 * tig + 1] = c[1];
            if (hiRow) {
                S.y[iq][gid + 8][n0 + 2 * tig]     = c[2];
                S.y[iq][gid + 8][n0 + 2 * tig + 1] = c[3];
            }
        }
        __syncthreads();
    }

    // ---- phase C: fused gathers + o_pair in one 128-iteration loop ----
    // threads 0..479: one gather output (o or o_pt); threads 0..383: also one o_pair output.
    {
        float ga0 = 0.0f, ga1 = 0.0f, ga2 = 0.0f, ga3 = 0.0f;   // gather accumulators
        float pa0 = 0.0f, pa1 = 0.0f, pa2 = 0.0f, pa3 = 0.0f;   // o_pair accumulators
        const bool doGather = (tid < 480);
        const bool doPair   = (tid < 384);
        const int ph = tid >> 5, pc = tid & 31;  // o_pair indices (valid when doPair)
        // gather addressing
        int gh = 0, goff = 0;
        const int* obase = S.o1;
        const float* gsrc = g_proj;
        if (doGather) {
            if (tid < 192) { gh = tid >> 4; goff = 384 + gh * 16 + (tid & 15); }
            else {
                int p = tid - 192;
                gh = p / 24; goff = gh * 36 + 12 + (p % 24);
                obase = S.o2; gsrc = g_kvpts;
            }
        }
#pragma unroll 8
        for (int k = 0; k < 128; k++) {
            if (doGather) {
                float v = __ldg(&gsrc[obase[k] + goff]);
                ga0 += S.logit[0][gh][k] * v;
                ga1 += S.logit[1][gh][k] * v;
                ga2 += S.logit[2][gh][k] * v;
                ga3 += S.logit[3][gh][k] * v;
            }
            if (doPair) {
                float w = __ldg(&g_Wzc[k * 44 + 12 + pc]);
                pa0 += S.y[0][ph][k] * w;
                pa1 += S.y[1][ph][k] * w;
                pa2 += S.y[2][ph][k] * w;
                pa3 += S.y[3][ph][k] * w;
            }
        }
        if (doGather) {
            if (tid < 192) {
                g_feats[(size_t)(row0 + 0) * FEATC_ + tid] = ga0;
                g_feats[(size_t)(row0 + 1) * FEATC_ + tid] = ga1;
                g_feats[(size_t)(row0 + 2) * FEATC_ + tid] = ga2;
                g_feats[(size_t)(row0 + 3) * FEATC_ + tid] = ga3;
            } else {
                int p = tid - 192;
                S.opt[0][p] = ga0; S.opt[1][p] = ga1;
                S.opt[2][p] = ga2; S.opt[3][p] = ga3;
            }
        }
        if (doPair) {
            g_feats[(size_t)(row0 + 0) * FEATC_ + 576 + tid] = pa0;
            g_feats[(size_t)(row0 + 1) * FEATC_ + 576 + tid] = pa1;
            g_feats[(size_t)(row0 + 2) * FEATC_ + 576 + tid] = pa2;
            g_feats[(size_t)(row0 + 3) * FEATC_ + 576 + tid] = pa3;
        }
    }
    __syncthreads();

    // ---- epilogue: inverse-frame transform + norms ----
    if (tid < 384) {
        int iq = tid / 96, j = tid % 96;
        int h = j >> 3, vp = j & 7;
        float* frow = g_feats + (size_t)(row0 + iq) * FEATC_;
        float X0 = S.opt[iq][h * 24 + vp * 3 + 0] - S.t[iq][0];
        float X1 = S.opt[iq][h * 24 + vp * 3 + 1] - S.t[iq][1];
        float X2 = S.opt[iq][h * 24 + vp * 3 + 2] - S.t[iq][2];
        float Y0 = S.R[iq][0] * X0 + S.R[iq][3] * X1 + S.R[iq][6] * X2;
        float Y1 = S.R[iq][1] * X0 + S.R[iq][4] * X1 + S.R[iq][7] * X2;
        float Y2 = S.R[iq][2] * X0 + S.R[iq][5] * X1 + S.R[iq][8] * X2;
        frow[192 + h * 24 + vp * 3 + 0] = Y0;
        frow[192 + h * 24 + vp * 3 + 1] = Y1;
        frow[192 + h * 24 + vp * 3 + 2] = Y2;
        frow[480 + h * 8 + vp] = sqrtf(Y0 * Y0 + Y1 * Y1 + Y2 * Y2 + 1e-8f);
    }
}

// -------- launch --------
extern "C" void kernel_launch(void* const* d_in, const int* in_sizes, int n_in,
                              void* d_out, int out_size) {
    const float* s       = (const float*)d_in[0];
    const float* z       = (const float*)d_in[1];
    const float* trans   = (const float*)d_in[2];
    const float* rots    = (const float*)d_in[3];
    const float* s_mask  = (const float*)d_in[4];
    const int*   key_idx = (const int*)d_in[5];
    const float* ln_s_g  = (const float*)d_in[6];
    const float* ln_s_b  = (const float*)d_in[7];
    const float* ln_z_g  = (const float*)d_in[8];
    const float* ln_z_b  = (const float*)d_in[9];
    const float* Wq      = (const float*)d_in[10];
    const float* Wk      = (const float*)d_in[11];
    const float* Wv      = (const float*)d_in[12];
    const float* Wqp     = (const float*)d_in[13];
    const float* Wkvp    = (const float*)d_in[14];
    const float* Wb      = (const float*)d_in[15];
    const float* Wdz     = (const float*)d_in[16];
    const float* hw      = (const float*)d_in[17];
    const float* Wout    = (const float*)d_in[18];
    float* out = (float*)d_out;

    void *p_sN, *p_Wcat, *p_proj, *p_feats;
    cudaGetSymbolAddress(&p_sN,    g_sN);
    cudaGetSymbolAddress(&p_Wcat,  g_Wcat);
    cudaGetSymbolAddress(&p_proj,  g_proj);
    cudaGetSymbolAddress(&p_feats, g_feats);

    cudaFuncSetAttribute(attn_kernel, cudaFuncAttributeMaxDynamicSharedMemorySize,
                         (int)sizeof(AttnSmem));

    prep_weights<<<256, 256>>>(Wq, Wk, Wv, Wqp, Wkvp, Wb, Wdz);
    ln_s_kernel<<<ROWS_, 128>>>(s, ln_s_g, ln_s_b);
    {
        dim3 grid(PROJC_ / 128, ROWS_ / 128);  // 9 x 32
        tgemm128<<<grid, 256>>>((const float*)p_sN, (const float*)p_Wcat,
                                (float*)p_proj, ROWS_, PROJC_, CS_);
    }
    postproj<<<ROWS_, 192>>>(rots, trans);
    attn_kernel<<<B_ * NB_ * 8, 512, sizeof(AttnSmem)>>>(z, trans, rots, s_mask, key_idx,
                                                         ln_z_g, ln_z_b, hw);
    {
        dim3 grid(CS_ / 128, ROWS_ / 128);     // 3 x 32
        tgemm128<<<grid, 256>>>((const float*)p_feats, Wout,
                                out, ROWS_, CS_, FEATC_);
    }
    (void)in_sizes; (void)n_in; (void)out_size;
}

// round 17
// speedup vs baseline: 1.6050x; 1.6050x over previous
#include <cuda_runtime.h>
#include <cuda_bf16.h>
#include <math.h>
#include <stdint.h>

// Problem constants
#define B_   2
#define N_   2048
#define BQ_  32
#define BK_  128
#define NB_  64
#define CS_  384
#define CZ_  128
#define CH_  16
#define H_   12
#define PQK_ 4
#define PV_  8
#define ROWS_ (B_ * N_)          // 4096
#define PROJC_ 1152
#define FEATC_ 960

// -------- scratch (static device globals; no allocation) --------
__device__ float g_sN   [ROWS_ * CS_];
__device__ float g_proj [ROWS_ * PROJC_];
__device__ float g_qpts [ROWS_ * 144];
__device__ float g_kvpts[ROWS_ * 432];
__device__ float g_qn   [ROWS_ * 12];
__device__ float g_kn   [ROWS_ * 12];
__device__ float g_feats[ROWS_ * FEATC_];
__device__ float g_Wcat [CS_ * PROJC_];
__device__ float g_Wzc  [CZ_ * 44];

// -------- helpers --------
__device__ __forceinline__ float warpSum(float v) {
#pragma unroll
    for (int o = 16; o; o >>= 1) v += __shfl_xor_sync(0xffffffffu, v, o);
    return v;
}
__device__ __forceinline__ float warpMax(float v) {
#pragma unroll
    for (int o = 16; o; o >>= 1) v = fmaxf(v, __shfl_xor_sync(0xffffffffu, v, o));
    return v;
}
__device__ __forceinline__ uint32_t f2tf32(float f) {
    uint32_t r;
    asm("cvt.rna.tf32.f32 %0, %1;" : "=r"(r) : "f"(f));
    return r;
}
__device__ __forceinline__ void mma_tf32(float* c, const uint32_t* a, const uint32_t* b) {
    asm volatile("mma.sync.aligned.m16n8k8.row.col.f32.tf32.tf32.f32 "
                 "{%0,%1,%2,%3}, {%4,%5,%6,%7}, {%8,%9}, {%0,%1,%2,%3};"
                 : "+f"(c[0]), "+f"(c[1]), "+f"(c[2]), "+f"(c[3])
                 : "r"(a[0]), "r"(a[1]), "r"(a[2]), "r"(a[3]), "r"(b[0]), "r"(b[1]));
}
// fp32-accurate MMA via 3-term tf32 split: c += a*b
__device__ __forceinline__ void mma_split(float* c, const float a[4], const float b[2]) {
    uint32_t ahi[4], alo[4], bhi[2], blo[2];
#pragma unroll
    for (int i = 0; i < 4; i++) {
        ahi[i] = f2tf32(a[i]);
        alo[i] = f2tf32(a[i] - __uint_as_float(ahi[i]));
    }
#pragma unroll
    for (int i = 0; i < 2; i++) {
        bhi[i] = f2tf32(b[i]);
        blo[i] = f2tf32(b[i] - __uint_as_float(bhi[i]));
    }
    mma_tf32(c, ahi, bhi);
    mma_tf32(c, ahi, blo);
    mma_tf32(c, alo, bhi);
}

// -------- weight prep --------
__global__ void prep_weights(const float* __restrict__ Wq, const float* __restrict__ Wk,
                             const float* __restrict__ Wv, const float* __restrict__ Wqp,
                             const float* __restrict__ Wkvp, const float* __restrict__ Wb,
                             const float* __restrict__ Wdz) {
    const int total1 = CS_ * PROJC_;
    const int total = total1 + CZ_ * 44;
    for (int i = blockIdx.x * blockDim.x + threadIdx.x; i < total; i += gridDim.x * blockDim.x) {
        if (i < total1) {
            int r = i / PROJC_, c = i % PROJC_;
            float w;
            if (c < 192)      w = Wq  [r * 192 + c] * 0.14433756729740643f;
            else if (c < 384) w = Wk  [r * 192 + (c - 192)];
            else if (c < 576) w = Wv  [r * 192 + (c - 384)];
            else if (c < 720) w = Wqp [r * 144 + (c - 576)];
            else              w = Wkvp[r * 432 + (c - 720)];
            g_Wcat[i] = w;
        } else {
            int j = i - total1;
            int r = j / 44, c = j % 44;
            g_Wzc[j] = (c < 12) ? Wb[r * 12 + c] * 0.5773502691896258f
                                : Wdz[r * 32 + (c - 12)];
        }
    }
}

// -------- LayerNorm of s --------
__global__ __launch_bounds__(128) void ln_s_kernel(const float* __restrict__ s,
                                                   const float* __restrict__ g,
                                                   const float* __restrict__ bb) {
    const int row = blockIdx.x;
    const int t = threadIdx.x;
    const float* x = s + (size_t)row * CS_;
    float a0 = x[t], a1 = x[t + 128], a2 = x[t + 256];
    float sum = a0 + a1 + a2;
    float sq = a0 * a0 + a1 * a1 + a2 * a2;
    __shared__ float rs[4], rq[4];
    float ws = warpSum(sum), wq = warpSum(sq);
    if ((t & 31) == 0) { rs[t >> 5] = ws; rq[t >> 5] = wq; }
    __syncthreads();
    float S = rs[0] + rs[1] + rs[2] + rs[3];
    float Q = rq[0] + rq[1] + rq[2] + rq[3];
    float m = S * (1.0f / 384.0f);
    float var = Q * (1.0f / 384.0f) - m * m;
    float inv = rsqrtf(var + 1e-5f);
    float* o = g_sN + (size_t)row * CS_;
    o[t]       = (a0 - m) * inv * g[t]       + bb[t];
    o[t + 128] = (a1 - m) * inv * g[t + 128] + bb[t + 128];
    o[t + 256] = (a2 - m) * inv * g[t + 256] + bb[t + 256];
}

// -------- tf32 tensor-core GEMM, 2-stage smem pipeline --------
__global__ __launch_bounds__(256) void tgemm128(const float* __restrict__ A,
                                                const float* __restrict__ B,
                                                float* __restrict__ C,
                                                int M, int N, int K) {
    __shared__ __align__(16) uint32_t As[2][16][136];
    __shared__ __align__(16) uint32_t Bs[2][16][136];
    const int tid = threadIdx.x;
    const int bm = blockIdx.y << 7, bn = blockIdx.x << 7;
    const int ar = tid >> 2, ac = (tid & 3) << 2;
    const int br = tid >> 5, bc = (tid & 31) << 2;
    const int warp = tid >> 5, lane = tid & 31;
    const int wm = (warp >> 2) * 64, wn = (warp & 3) * 32;
    const int gid = lane >> 2, tig = lane & 3;

    const float* Ap = A + (size_t)(bm + ar) * K + ac;
    const float* Bp = B + (size_t)br * N + bn + bc;
    const size_t A64 = (size_t)64 * K;
    const size_t B8  = (size_t)8 * N;

    float4 pa0 = *reinterpret_cast<const float4*>(Ap);
    float4 pa1 = *reinterpret_cast<const float4*>(Ap + A64);
    float4 pb0 = *reinterpret_cast<const float4*>(Bp);
    float4 pb1 = *reinterpret_cast<const float4*>(Bp + B8);

    As[0][ac + 0][ar] = f2tf32(pa0.x); As[0][ac + 1][ar] = f2tf32(pa0.y);
    As[0][ac + 2][ar] = f2tf32(pa0.z); As[0][ac + 3][ar] = f2tf32(pa0.w);
    As[0][ac + 0][ar + 64] = f2tf32(pa1.x); As[0][ac + 1][ar + 64] = f2tf32(pa1.y);
    As[0][ac + 2][ar + 64] = f2tf32(pa1.z); As[0][ac + 3][ar + 64] = f2tf32(pa1.w);
    Bs[0][br][bc + 0] = f2tf32(pb0.x); Bs[0][br][bc + 1] = f2tf32(pb0.y);
    Bs[0][br][bc + 2] = f2tf32(pb0.z); Bs[0][br][bc + 3] = f2tf32(pb0.w);
    Bs[0][br + 8][bc + 0] = f2tf32(pb1.x); Bs[0][br + 8][bc + 1] = f2tf32(pb1.y);
    Bs[0][br + 8][bc + 2] = f2tf32(pb1.z); Bs[0][br + 8][bc + 3] = f2tf32(pb1.w);
    __syncthreads();

    float acc[16][4] = {};
    const int ktiles = K >> 4;
    for (int kt = 0; kt < ktiles; kt++) {
        const int cur = kt & 1;
        const bool more = (kt + 1 < ktiles);
        if (more) {
            Ap += 16; Bp += (size_t)16 * N;
            pa0 = *reinterpret_cast<const float4*>(Ap);
            pa1 = *reinterpret_cast<const float4*>(Ap + A64);
            pb0 = *reinterpret_cast<const float4*>(Bp);
            pb1 = *reinterpret_cast<const float4*>(Bp + B8);
        }
#pragma unroll
        for (int kk = 0; kk < 16; kk += 8) {
            uint32_t af[4][4], bf[4][2];
#pragma unroll
            for (int mt = 0; mt < 4; mt++) {
                int m = wm + mt * 16 + gid;
                af[mt][0] = As[cur][kk + tig][m];
                af[mt][1] = As[cur][kk + tig][m + 8];
                af[mt][2] = As[cur][kk + tig + 4][m];
                af[mt][3] = As[cur][kk + tig + 4][m + 8];
            }
#pragma unroll
            for (int nt = 0; nt < 4; nt++) {
                int n = wn + nt * 8 + gid;
                bf[nt][0] = Bs[cur][kk + tig][n];
                bf[nt][1] = Bs[cur][kk + tig + 4][n];
            }
#pragma unroll
            for (int mt = 0; mt < 4; mt++)
#pragma unroll
                for (int nt = 0; nt < 4; nt++)
                    mma_tf32(acc[mt * 4 + nt], af[mt], bf[nt]);
        }
        if (more) {
            const int nxt = cur ^ 1;
            As[nxt][ac + 0][ar] = f2tf32(pa0.x); As[nxt][ac + 1][ar] = f2tf32(pa0.y);
            As[nxt][ac + 2][ar] = f2tf32(pa0.z); As[nxt][ac + 3][ar] = f2tf32(pa0.w);
            As[nxt][ac + 0][ar + 64] = f2tf32(pa1.x); As[nxt][ac + 1][ar + 64] = f2tf32(pa1.y);
            As[nxt][ac + 2][ar + 64] = f2tf32(pa1.z); As[nxt][ac + 3][ar + 64] = f2tf32(pa1.w);
            Bs[nxt][br][bc + 0] = f2tf32(pb0.x); Bs[nxt][br][bc + 1] = f2tf32(pb0.y);
            Bs[nxt][br][bc + 2] = f2tf32(pb0.z); Bs[nxt][br][bc + 3] = f2tf32(pb0.w);
            Bs[nxt][br + 8][bc + 0] = f2tf32(pb1.x); Bs[nxt][br + 8][bc + 1] = f2tf32(pb1.y);
            Bs[nxt][br + 8][bc + 2] = f2tf32(pb1.z); Bs[nxt][br + 8][bc + 3] = f2tf32(pb1.w);
            __syncthreads();
        }
    }
#pragma unroll
    for (int mt = 0; mt < 4; mt++) {
#pragma unroll
        for (int nt = 0; nt < 4; nt++) {
            const float* a = acc[mt * 4 + nt];
            int r0 = bm + wm + mt * 16 + gid;
            int c0 = bn + wn + nt * 8 + tig * 2;
            float2 lo = make_float2(a[0], a[1]);
            float2 hi = make_float2(a[2], a[3]);
            *reinterpret_cast<float2*>(&C[(size_t)r0 * N + c0]) = lo;
            *reinterpret_cast<float2*>(&C[(size_t)(r0 + 8) * N + c0]) = hi;
        }
    }
}

// -------- per-row point rotation + norms --------
__global__ __launch_bounds__(192) void postproj(const float* __restrict__ rots,
                                                const float* __restrict__ trans) {
    const int row = blockIdx.x;
    const int t = threadIdx.x;
    __shared__ float R[9], T[3], nrm[24];
    if (t < 9)  R[t] = rots[row * 9 + t];
    if (t < 3)  T[t] = trans[row * 3 + t];
    if (t < 24) nrm[t] = 0.0f;
    __syncthreads();
    const float* pr = g_proj + (size_t)row * PROJC_;
    float x, y, zz;
    if (t < 48) {
        x = pr[576 + t * 3]; y = pr[576 + t * 3 + 1]; zz = pr[576 + t * 3 + 2];
    } else {
        int j = t - 48;
        x = pr[720 + j * 3]; y = pr[720 + j * 3 + 1]; zz = pr[720 + j * 3 + 2];
    }
    float rx = R[0] * x + R[1] * y + R[2] * zz + T[0];
    float ry = R[3] * x + R[4] * y + R[5] * zz + T[1];
    float rz = R[6] * x + R[7] * y + R[8] * zz + T[2];
    float sq = rx * rx + ry * ry + rz * rz;
    if (t < 48) {
        g_qpts[row * 144 + t * 3 + 0] = rx;
        g_qpts[row * 144 + t * 3 + 1] = ry;
        g_qpts[row * 144 + t * 3 + 2] = rz;
        atomicAdd(&nrm[t >> 2], sq);
    } else {
        int j = t - 48;
        g_kvpts[(size_t)row * 432 + j * 3 + 0] = rx;
        g_kvpts[(size_t)row * 432 + j * 3 + 1] = ry;
        g_kvpts[(size_t)row * 432 + j * 3 + 2] = rz;
        if ((j % 12) < 4) atomicAdd(&nrm[12 + j / 12], sq);
    }
    __syncthreads();
    if (t < 12)       g_qn[row * 12 + t] = nrm[t];
    else if (t < 24)  g_kn[row * 12 + (t - 12)] = nrm[t];
}

// -------- fused attention kernel: one block per (b, nb, group of 4 q) --------
struct AttnSmem {
    float zn[128][132];        // LN'd z for the CURRENT q (reused across the 4 q)
    float logit[4][12][132];   // logit base -> +bbias -> probs (row pad 132 for MMA)
    float y[4][12][128];       // a @ zn per q
    uint32_t WbTh[16][132];    // pre-split (hi) transposed bbias weights
    uint32_t WbTl[16][132];    // pre-split (lo)
    uint32_t pHi[12][132];     // pre-split probs (hi) for CURRENT q
    uint32_t pLo[12][132];     // pre-split probs (lo)
    float q[4][192];
    float qpts[4][144];
    float qn[4][12];
    float hw[12];
    float R[4][9], t[4][3];
    float km[128];
    float qm[4];
    float opt[4][288];
    int   o1[128], o2[128], o3[128];
};

__global__ __launch_bounds__(512) void attn_kernel(const float* __restrict__ z,
                                                   const float* __restrict__ trans,
                                                   const float* __restrict__ rots,
                                                   const float* __restrict__ s_mask,
                                                   const int* __restrict__ key_idx,
                                                   const float* __restrict__ ln_z_g,
                                                   const float* __restrict__ ln_z_b,
                                                   const float* __restrict__ head_w) {
    extern __shared__ __align__(16) char smem_raw[];
    AttnSmem& S = *reinterpret_cast<AttnSmem*>(smem_raw);

    const int blk = blockIdx.x;
    const int b  = blk >> 9;
    const int nb = (blk >> 3) & 63;
    const int q0 = (blk & 7) * 4;
    const int tid = threadIdx.x;
    const int lane = tid & 31, warp = tid >> 5;
    const int gid = lane >> 2, tig = lane & 3;
    const int row0 = b * N_ + nb * 32 + q0;

    // ---- prefetch q0's z into registers immediately ----
    const float4* zb_base = reinterpret_cast<const float4*>(
        z + ((size_t)((b * 64 + nb) * 32 + q0) * 128) * 128);
    float4 zr[8];
#pragma unroll
    for (int j = 0; j < 8; j++)
        zr[j] = zb_base[(size_t)(warp * 8 + j) * 32 + lane];

    // ---- init ----
    for (int k = tid; k < 128; k += 512) {
        int nk = key_idx[nb * 128 + k];
        int kr = b * N_ + nk;
        S.o1[k] = kr * PROJC_;
        S.o2[k] = kr * 432;
        S.o3[k] = kr * 12;
        S.km[k] = s_mask[kr];
    }
    for (int i = tid; i < 16 * 132; i += 512) {
        int col = i / 132, c = i % 132;
        float w = (col < 12 && c < 128) ? g_Wzc[c * 44 + col] : 0.0f;
        uint32_t hi = f2tf32(w);
        S.WbTh[col][c] = hi;
        S.WbTl[col][c] = f2tf32(w - __uint_as_float(hi));
    }
    for (int i = tid; i < 4 * 192; i += 512)
        S.q[i / 192][i % 192] = g_proj[(size_t)(row0 + i / 192) * PROJC_ + i % 192];
    for (int i = tid; i < 4 * 144; i += 512)
        S.qpts[i / 144][i % 144] = g_qpts[(row0 + i / 144) * 144 + i % 144];
    if (tid < 48) S.qn[tid / 12][tid % 12] = g_qn[(row0 + tid / 12) * 12 + tid % 12];
    if (tid < 36) S.R[tid / 9][tid % 9] = rots[(row0 + tid / 9) * 9 + tid % 9];
    if (tid >= 64 && tid < 76) S.t[(tid - 64) / 3][(tid - 64) % 3] = trans[(row0 + (tid - 64) / 3) * 3 + (tid - 64) % 3];
    if (tid >= 96 && tid < 100) S.qm[tid - 96] = s_mask[row0 + (tid - 96)];
    if (tid >= 128 && tid < 140) {
        float hx = head_w[tid - 128];
        float sp = fmaxf(hx, 0.0f) + log1pf(expf(-fabsf(hx)));
        S.hw[tid - 128] = -0.5f * sp * 0.13608276348795434f;
    }
    __syncthreads();

    // ---- phase A: logit base for all 4 q (gathers amortized 4x) ----
#pragma unroll
    for (int l = tid; l < 1536; l += 512) {
        int h = l >> 7, k = l & 127;
        const float* kp = g_proj + S.o1[k] + 192 + h * 16;
        float4 k0 = __ldg((const float4*)(kp));
        float4 k1 = __ldg((const float4*)(kp + 4));
        float4 k2 = __ldg((const float4*)(kp + 8));
        float4 k3 = __ldg((const float4*)(kp + 12));
        const float* kpt = g_kvpts + S.o2[k] + h * 36;
        float4 p0 = __ldg((const float4*)(kpt));
        float4 p1 = __ldg((const float4*)(kpt + 4));
        float4 p2 = __ldg((const float4*)(kpt + 8));
        float knv = __ldg(&g_kn[S.o3[k] + h]);
        const float hwv = S.hw[h];
        const float kmv = S.km[k];
#pragma unroll
        for (int i = 0; i < 4; i++) {
            float4 q0v = *reinterpret_cast<const float4*>(&S.q[i][h * 16]);
            float4 q1v = *reinterpret_cast<const float4*>(&S.q[i][h * 16 + 4]);
            float4 q2v = *reinterpret_cast<const float4*>(&S.q[i][h * 16 + 8]);
            float4 q3v = *reinterpret_cast<const float4*>(&S.q[i][h * 16 + 12]);
            float4 s0 = *reinterpret_cast<const float4*>(&S.qpts[i][h * 12]);
            float4 s1 = *reinterpret_cast<const float4*>(&S.qpts[i][h * 12 + 4]);
            float4 s2 = *reinterpret_cast<const float4*>(&S.qpts[i][h * 12 + 8]);
            float dot = k0.x * q0v.x + k0.y * q0v.y + k0.z * q0v.z + k0.w * q0v.w
                      + k1.x * q1v.x + k1.y * q1v.y + k1.z * q1v.z + k1.w * q1v.w
                      + k2.x * q2v.x + k2.y * q2v.y + k2.z * q2v.z + k2.w * q2v.w
                      + k3.x * q3v.x + k3.y * q3v.y + k3.z * q3v.z + k3.w * q3v.w;
            float pdot = p0.x * s0.x + p0.y * s0.y + p0.z * s0.z + p0.w * s0.w
                       + p1.x * s1.x + p1.y * s1.y + p1.z * s1.z + p1.w * s1.w
                       + p2.x * s2.x + p2.y * s2.y + p2.z * s2.z + p2.w * s2.w;
            float pt = -2.0f * pdot + S.qn[i][h] + knv;
            S.logit[i][h][k] = dot + hwv * pt + 100000.0f * (S.qm[i] * kmv - 1.0f);
        }
    }
    __syncthreads();

    // ---- phase B: per q: LN(regs) -> bbias(MMA) -> softmax -> y(MMA) ----
    const float4 gv = reinterpret_cast<const float4*>(ln_z_g)[lane];
    const float4 bv = reinterpret_cast<const float4*>(ln_z_b)[lane];
    for (int iq = 0; iq < 4; iq++) {
#pragma unroll
        for (int i = 0; i < 4; i++) {
            const int k0 = warp * 8 + i * 2;
            float4 u = zr[i * 2], w = zr[i * 2 + 1];
            float su = u.x + u.y + u.z + u.w;
            float sw = w.x + w.y + w.z + w.w;
            float qu = u.x * u.x + u.y * u.y + u.z * u.z + u.w * u.w;
            float qw = w.x * w.x + w.y * w.y + w.z * w.z + w.w * w.w;
            float mu = warpSum(su) * (1.0f / 128.0f);
            float mw = warpSum(sw) * (1.0f / 128.0f);
            float vu = warpSum(qu) * (1.0f / 128.0f) - mu * mu;
            float vw = warpSum(qw) * (1.0f / 128.0f) - mw * mw;
            float iu = rsqrtf(vu + 1e-5f);
            float iw = rsqrtf(vw + 1e-5f);
            float4 ou, ow;
            ou.x = (u.x - mu) * iu * gv.x + bv.x; ou.y = (u.y - mu) * iu * gv.y + bv.y;
            ou.z = (u.z - mu) * iu * gv.z + bv.z; ou.w = (u.w - mu) * iu * gv.w + bv.w;
            ow.x = (w.x - mw) * iw * gv.x + bv.x; ow.y = (w.y - mw) * iw * gv.y + bv.y;
            ow.z = (w.z - mw) * iw * gv.z + bv.z; ow.w = (w.w - mw) * iw * gv.w + bv.w;
            *reinterpret_cast<float4*>(&S.zn[k0][lane * 4])     = ou;
            *reinterpret_cast<float4*>(&S.zn[k0 + 1][lane * 4]) = ow;
        }
        if (iq < 3) {
            const float4* zb = zb_base + (size_t)(iq + 1) * 4096;
#pragma unroll
            for (int j = 0; j < 8; j++)
                zr[j] = zb[(size_t)(warp * 8 + j) * 32 + lane];
        }
        __syncthreads();

        // bbias via MMA: bb[128key, 12col] = zn[128,128] @ Wb[128,12]
        // b operand pre-split (constant across iq); a split inline.
        {
            const int mt = warp >> 1, nt = warp & 1;
            const int m0 = mt * 16, n0 = nt * 8;
            float c[4] = {};
#pragma unroll
            for (int ko = 0; ko < 128; ko += 8) {
                float a[4];
                a[0] = S.zn[m0 + gid][ko + tig];
                a[1] = S.zn[m0 + gid + 8][ko + tig];
                a[2] = S.zn[m0 + gid][ko + tig + 4];
                a[3] = S.zn[m0 + gid + 8][ko + tig + 4];
                uint32_t ahi[4], alo[4], bhi[2], blo[2];
#pragma unroll
                for (int i = 0; i < 4; i++) {
                    ahi[i] = f2tf32(a[i]);
                    alo[i] = f2tf32(a[i] - __uint_as_float(ahi[i]));
                }
                bhi[0] = S.WbTh[n0 + gid][ko + tig];
                bhi[1] = S.WbTh[n0 + gid][ko + tig + 4];
                blo[0] = S.WbTl[n0 + gid][ko + tig];
                blo[1] = S.WbTl[n0 + gid][ko + tig + 4];
                mma_tf32(c, ahi, bhi);
                mma_tf32(c, ahi, blo);
                mma_tf32(c, alo, bhi);
            }
            const int col0 = n0 + 2 * tig;
            if (col0 < 12) {
                S.logit[iq][col0][m0 + gid]     += c[0];
                S.logit[iq][col0][m0 + gid + 8] += c[2];
            }
            if (col0 + 1 < 12) {
                S.logit[iq][col0 + 1][m0 + gid]     += c[1];
                S.logit[iq][col0 + 1][m0 + gid + 8] += c[3];
            }
        }
        __syncthreads();

        // softmax (also writes pre-split tf32 probs for the y MMA)
        if (warp < 12) {
            const int h = warp;
            float v0 = S.logit[iq][h][lane],      v1 = S.logit[iq][h][lane + 32];
            float v2 = S.logit[iq][h][lane + 64], v3 = S.logit[iq][h][lane + 96];
            float mx = warpMax(fmaxf(fmaxf(v0, v1), fmaxf(v2, v3)));
            v0 = expf(v0 - mx); v1 = expf(v1 - mx); v2 = expf(v2 - mx); v3 = expf(v3 - mx);
            float invs = 1.0f / warpSum(v0 + v1 + v2 + v3);
            v0 *= invs; v1 *= invs; v2 *= invs; v3 *= invs;
            S.logit[iq][h][lane]      = v0;
            S.logit[iq][h][lane + 32] = v1;
            S.logit[iq][h][lane + 64] = v2;
            S.logit[iq][h][lane + 96] = v3;
            uint32_t h0 = f2tf32(v0), h1 = f2tf32(v1), h2 = f2tf32(v2), h3 = f2tf32(v3);
            S.pHi[h][lane]      = h0;  S.pLo[h][lane]      = f2tf32(v0 - __uint_as_float(h0));
            S.pHi[h][lane + 32] = h1;  S.pLo[h][lane + 32] = f2tf32(v1 - __uint_as_float(h1));
            S.pHi[h][lane + 64] = h2;  S.pLo[h][lane + 64] = f2tf32(v2 - __uint_as_float(h2));
            S.pHi[h][lane + 96] = h3;  S.pLo[h][lane + 96] = f2tf32(v3 - __uint_as_float(h3));
        }
        __syncthreads();

        // y via MMA: y[12h, 128cz] = a[12,128k] @ zn[128k,128cz]
        // a operand pre-split (shared by all 16 warps); b split inline.
        {
            const int n0 = warp * 8;
            float c[4] = {};
            const bool hiRow = (gid + 8 < 12);
#pragma unroll
            for (int ko = 0; ko < 128; ko += 8) {
                uint32_t ahi[4], alo[4], bhi[2], blo[2];
                ahi[0] = S.pHi[gid][ko + tig];
                alo[0] = S.pLo[gid][ko + tig];
                ahi[1] = hiRow ? S.pHi[gid + 8][ko + tig] : 0u;
                alo[1] = hiRow ? S.pLo[gid + 8][ko + tig] : 0u;
                ahi[2] = S.pHi[gid][ko + tig + 4];
                alo[2] = S.pLo[gid][ko + tig + 4];
                ahi[3] = hiRow ? S.pHi[gid + 8][ko + tig + 4] : 0u;
                alo[3] = hiRow ? S.pLo[gid + 8][ko + tig + 4] : 0u;
                float b0 = S.zn[ko + tig][n0 + gid];
                float b1 = S.zn[ko + tig + 4][n0 + gid];
                bhi[0] = f2tf32(b0);
                blo[0] = f2tf32(b0 - __uint_as_float(bhi[0]));
                bhi[1] = f2tf32(b1);
                blo[1] = f2tf32(b1 - __uint_as_float(bhi[1]));
                mma_tf32(c, ahi, bhi);
                mma_tf32(c, ahi, blo);
                mma_tf32(c, alo, bhi);
            }
            S.y[iq][gid][n0 + 2 * tig]     = c[0];
            S.y[iq][gid][n0 + 2 * tig + 1] = c[1];
            if (hiRow) {
                S.y[iq][gid + 8][n0 + 2 * tig]     = c[2];
                S.y[iq][gid + 8][n0 + 2 * tig + 1] = c[3];
            }
        }
        __syncthreads();
    }

    // ---- phase C: o/o_pt gathers (amortized 4x) + o_pair ----
    for (int o = tid; o < 864; o += 512) {
        float acc0 = 0.0f, acc1 = 0.0f, acc2 = 0.0f, acc3 = 0.0f;
        if (o < 192) {
            int h = o >> 4, c = o & 15;
            const int off = 384 + h * 16 + c;
#pragma unroll 8
            for (int k = 0; k < 128; k++) {
                float v = __ldg(&g_proj[S.o1[k] + off]);
                acc0 += S.logit[0][h][k] * v;
                acc1 += S.logit[1][h][k] * v;
                acc2 += S.logit[2][h][k] * v;
                acc3 += S.logit[3][h][k] * v;
            }
            g_feats[(size_t)(row0 + 0) * FEATC_ + o] = acc0;
            g_feats[(size_t)(row0 + 1) * FEATC_ + o] = acc1;
            g_feats[(size_t)(row0 + 2) * FEATC_ + o] = acc2;
            g_feats[(size_t)(row0 + 3) * FEATC_ + o] = acc3;
        } else if (o < 480) {
            int p = o - 192;
            int h = p / 24, r = p % 24;
            const int off = h * 36 + 12 + r;
#pragma unroll 8
            for (int k = 0; k < 128; k++) {
                float v = __ldg(&g_kvpts[S.o2[k] + off]);
                acc0 += S.logit[0][h][k] * v;
                acc1 += S.logit[1][h][k] * v;
                acc2 += S.logit[2][h][k] * v;
                acc3 += S.logit[3][h][k] * v;
            }
            S.opt[0][p] = acc0; S.opt[1][p] = acc1;
            S.opt[2][p] = acc2; S.opt[3][p] = acc3;
        } else {
            int p = o - 480;
            int h = p >> 5, c = p & 31;
#pragma unroll 8
            for (int cz = 0; cz < 128; cz++) {
                float w = __ldg(&g_Wzc[cz * 44 + 12 + c]);
                acc0 += S.y[0][h][cz] * w;
                acc1 += S.y[1][h][cz] * w;
                acc2 += S.y[2][h][cz] * w;
                acc3 += S.y[3][h][cz] * w;
            }
            g_feats[(size_t)(row0 + 0) * FEATC_ + 576 + p] = acc0;
            g_feats[(size_t)(row0 + 1) * FEATC_ + 576 + p] = acc1;
            g_feats[(size_t)(row0 + 2) * FEATC_ + 576 + p] = acc2;
            g_feats[(size_t)(row0 + 3) * FEATC_ + 576 + p] = acc3;
        }
    }
    __syncthreads();

    // ---- epilogue: inverse-frame transform + norms ----
    if (tid < 384) {
        int iq = tid / 96, j = tid % 96;
        int h = j >> 3, vp = j & 7;
        float* frow = g_feats + (size_t)(row0 + iq) * FEATC_;
        float X0 = S.opt[iq][h * 24 + vp * 3 + 0] - S.t[iq][0];
        float X1 = S.opt[iq][h * 24 + vp * 3 + 1] - S.t[iq][1];
        float X2 = S.opt[iq][h * 24 + vp * 3 + 2] - S.t[iq][2];
        float Y0 = S.R[iq][0] * X0 + S.R[iq][3] * X1 + S.R[iq][6] * X2;
        float Y1 = S.R[iq][1] * X0 + S.R[iq][4] * X1 + S.R[iq][7] * X2;
        float Y2 = S.R[iq][2] * X0 + S.R[iq][5] * X1 + S.R[iq][8] * X2;
        frow[192 + h * 24 + vp * 3 + 0] = Y0;
        frow[192 + h * 24 + vp * 3 + 1] = Y1;
        frow[192 + h * 24 + vp * 3 + 2] = Y2;
        frow[480 + h * 8 + vp] = sqrtf(Y0 * Y0 + Y1 * Y1 + Y2 * Y2 + 1e-8f);
    }
}

// -------- launch --------
extern "C" void kernel_launch(void* const* d_in, const int* in_sizes, int n_in,
                              void* d_out, int out_size) {
    const float* s       = (const float*)d_in[0];
    const float* z       = (const float*)d_in[1];
    const float* trans   = (const float*)d_in[2];
    const float* rots    = (const float*)d_in[3];
    const float* s_mask  = (const float*)d_in[4];
    const int*   key_idx = (const int*)d_in[5];
    const float* ln_s_g  = (const float*)d_in[6];
    const float* ln_s_b  = (const float*)d_in[7];
    const float* ln_z_g  = (const float*)d_in[8];
    const float* ln_z_b  = (const float*)d_in[9];
    const float* Wq      = (const float*)d_in[10];
    const float* Wk      = (const float*)d_in[11];
    const float* Wv      = (const float*)d_in[12];
    const float* Wqp     = (const float*)d_in[13];
    const float* Wkvp    = (const float*)d_in[14];
    const float* Wb      = (const float*)d_in[15];
    const float* Wdz     = (const float*)d_in[16];
    const float* hw      = (const float*)d_in[17];
    const float* Wout    = (const float*)d_in[18];
    float* out = (float*)d_out;

    void *p_sN, *p_Wcat, *p_proj, *p_feats;
    cudaGetSymbolAddress(&p_sN,    g_sN);
    cudaGetSymbolAddress(&p_Wcat,  g_Wcat);
    cudaGetSymbolAddress(&p_proj,  g_proj);
    cudaGetSymbolAddress(&p_feats, g_feats);

    cudaFuncSetAttribute(attn_kernel, cudaFuncAttributeMaxDynamicSharedMemorySize,
                         (int)sizeof(AttnSmem));

    prep_weights<<<256, 256>>>(Wq, Wk, Wv, Wqp, Wkvp, Wb, Wdz);
    ln_s_kernel<<<ROWS_, 128>>>(s, ln_s_g, ln_s_b);
    {
        dim3 grid(PROJC_ / 128, ROWS_ / 128);  // 9 x 32
        tgemm128<<<grid, 256>>>((const float*)p_sN, (const float*)p_Wcat,
                                (float*)p_proj, ROWS_, PROJC_, CS_);
    }
    postproj<<<ROWS_, 192>>>(rots, trans);
    attn_kernel<<<B_ * NB_ * 8, 512, sizeof(AttnSmem)>>>(z, trans, rots, s_mask, key_idx,
                                                         ln_z_g, ln_z_b, hw);
    {
        dim3 grid(CS_ / 128, ROWS_ / 128);     // 3 x 32
        tgemm128<<<grid, 256>>>((const float*)p_feats, Wout,
                                out, ROWS_, CS_, FEATC_);
    }
    (void)in_sizes; (void)n_in; (void)out_size;
}